// round 8
// baseline (speedup 1.0000x reference)
#include <cuda_runtime.h>
#include <cuda_fp16.h>

#define D  64
#define NA 64
#define MAX_ITEM 100000
#define MAX_BZ   1024

// Scratch tables (allocation-free: __device__ globals)
__device__ __align__(16) __half g_Ph[MAX_BZ * NA];             // 128 KB fp16 P
__device__ __align__(16) __half g_Qh[(size_t)MAX_ITEM * NA];   // 12.8 MB fp16 Qd+bias

// ---- packed f32x2 FMA (Blackwell): acc = a*b + acc, lanewise on 2 floats ----
__device__ __forceinline__ void ffma2(unsigned long long& acc,
                                      unsigned long long a,
                                      unsigned long long b) {
    asm("fma.rn.f32x2 %0, %1, %2, %0;" : "+l"(acc) : "l"(a), "l"(b));
}
union F2U { float2 f; unsigned long long u; };
union F4U { float4 f; struct { unsigned long long lo, hi; } u; };

// A row stride: 68 floats = 272 B. 16B-aligned rows (272%16==0) AND
// inter-lane bank stride 68%32==4 -> each 8-lane LDS.128 phase hits distinct
// bank quads 4k..4k+3: conflict-free at the 4-wavefront floor.
#define A_STRIDE 68

// ---------------------------------------------------------------------------
// Fused prep: blocks [0, QB) -> fp16 Qd table (+bias folded); [QB,QB+PB) -> P.
// Lane owns aspects (l, l+32). FFMA2 pairs over (d, d+1): acc is a float2 of
// d-even/d-odd partials, one horizontal add at the end. Item side = LDS.128
// broadcast (1 wf), A side = per-lane LDS.128 (4 wf floor).
// Per 4d / 8 items: 10 LDS + 32 FFMA2.
// ---------------------------------------------------------------------------
__global__ void __launch_bounds__(256) prep_kernel(
        const int* __restrict__ uidx,
        const float* __restrict__ Uemb,
        const float* __restrict__ Iemb,
        const float* __restrict__ A,
        const float* __restrict__ Rel,
        const float* __restrict__ bias,
        int bz, int nitem, int QB) {
    __shared__ __align__(16) float  A_s[64 * A_STRIDE];  // 17.4 KB row-major padded
    __shared__ __align__(16) float  sR[128];             // qd: RpA|RnA ; p: RuA
    __shared__ __align__(16) float4 Ism[8][128];         // 8 items x 64 f /warp

    int t = threadIdx.x;
    for (int idx = t; idx < 64 * 64; idx += 256)
        A_s[(idx >> 6) * A_STRIDE + (idx & 63)] = A[idx];  // coalesced fill
    __syncthreads();

    int w = t >> 5, lane = t & 31;
    bool isQ = blockIdx.x < QB;

    // ---- per-block relation projections (A from smem, Rel broadcast) ----
    if (isQ) {
        if (t < 128) {
            int rr = 1 + (t >> 6);       // 1 = Rip, 2 = Rin
            int a  = t & 63;
            const float* rv = Rel + rr * D;
            const float* ar = A_s + a * A_STRIDE;
            float s = 0.f;
#pragma unroll
            for (int d = 0; d < 64; d++) s += rv[d] * ar[d];
            sR[t] = s;                    // [0,64)=RpA, [64,128)=RnA
        }
    } else {
        if (t < 64) {
            const float* ar = A_s + t * A_STRIDE;
            float s = 0.f;
#pragma unroll
            for (int d = 0; d < 64; d++) s += Rel[d] * ar[d];
            sR[t] = s;                    // RuA
        }
    }
    __syncthreads();

    if (isQ) {
        // ======== Qd blocks: 8 warps x 8 items = 64 items/block ========
        float rp0 = sR[lane],      rp1 = sR[lane + 32];   // aspects l, l+32
        float rn0 = sR[64 + lane], rn1 = sR[96 + lane];
        int base8 = blockIdx.x * 64 + w * 8;              // 8 consecutive items
        if (base8 < nitem) {                              // nitem % 8 == 0
            // Item tile: straight linear copy, conflict-free, coalesced.
            const float4* g4 = (const float4*)(Iemb + (size_t)base8 * D);
#pragma unroll
            for (int u = 0; u < 4; u++) Ism[w][lane + 32 * u] = g4[lane + 32 * u];
            __syncwarp();

            unsigned long long acc[8][2];
#pragma unroll
            for (int j = 0; j < 8; j++) { acc[j][0] = 0ull; acc[j][1] = 0ull; }

            const float* Arow0 = A_s + lane * A_STRIDE;          // aspect l
            const float* Arow1 = A_s + (lane + 32) * A_STRIDE;   // aspect l+32
            const float4* irow = Ism[w];
#pragma unroll 4
            for (int dc = 0; dc < 16; dc++) {          // 4 d per iteration
                F4U a0; a0.f = *(const float4*)(Arow0 + 4 * dc);   // LDS.128 cf
                F4U a1; a1.f = *(const float4*)(Arow1 + 4 * dc);   // LDS.128 cf
#pragma unroll
                for (int j = 0; j < 8; j++) {
                    F4U iv; iv.f = irow[j * 16 + dc];              // LDS.128 bcast
                    ffma2(acc[j][0], iv.u.lo, a0.u.lo);
                    ffma2(acc[j][1], iv.u.lo, a1.u.lo);
                    ffma2(acc[j][0], iv.u.hi, a0.u.hi);
                    ffma2(acc[j][1], iv.u.hi, a1.u.hi);
                }
            }

#pragma unroll
            for (int j = 0; j < 8; j++) {
                F2U c0; c0.u = acc[j][0];
                F2U c1; c1.u = acc[j][1];
                float L0 = c0.f.x + c0.f.y;           // horizontal d-combine
                float L1 = c1.f.x + c1.f.y;
                // shift-free softmax: |logit| <~ 50 << 88 (fp32 exp overflow)
                float ep0 = __expf(L0 + rp0), ep1 = __expf(L1 + rp1);
                float en0 = __expf(L0 + rn0), en1 = __expf(L1 + rn1);
                float sp = ep0 + ep1, sn = en0 + en1;
#pragma unroll
                for (int o = 16; o; o >>= 1) {
                    sp += __shfl_xor_sync(0xffffffffu, sp, o);
                    sn += __shfl_xor_sync(0xffffffffu, sn, o);
                }
                float ipv = __fdividef(1.f, sp);
                float inv = __fdividef(1.f, sn);
                float bb  = bias[base8 + j];          // warp-uniform broadcast
                __half* orow = g_Qh + (size_t)(base8 + j) * NA;
                orow[lane]      = __float2half_rn(ep0 * ipv - en0 * inv + bb);
                orow[lane + 32] = __float2half_rn(ep1 * ipv - en1 * inv + bb);
            }
        }
    } else {
        // ================= P blocks: 8 users/block =================
        float ru0 = sR[lane], ru1 = sR[lane + 32];
        int row = (blockIdx.x - QB) * 8 + w;
        if (row >= bz) return;
        const float* U = Uemb + (size_t)uidx[row] * D;
        float* us = (float*)Ism[w];
        ((float2*)us)[lane] = ((const float2*)U)[lane];
        __syncwarp();

        const float* Arow0 = A_s + lane * A_STRIDE;
        const float* Arow1 = A_s + (lane + 32) * A_STRIDE;
        float acc0 = 0.f, acc1 = 0.f;
#pragma unroll
        for (int d = 0; d < 64; d++) {
            float u = us[d];
            acc0 += u * Arow0[d];
            acc1 += u * Arow1[d];
        }
        float l0 = acc0 + ru0, l1 = acc1 + ru1;
        float m = fmaxf(l0, l1);
#pragma unroll
        for (int o = 16; o; o >>= 1) m = fmaxf(m, __shfl_xor_sync(0xffffffffu, m, o));
        float e0 = __expf(l0 - m), e1 = __expf(l1 - m);
        float s = e0 + e1;
#pragma unroll
        for (int o = 16; o; o >>= 1) s += __shfl_xor_sync(0xffffffffu, s, o);
        float inv = __fdividef(1.f, s);
        __half* prow = g_Ph + row * NA;
        prow[lane]      = __float2half_rn(e0 * inv);
        prow[lane + 32] = __float2half_rn(e1 * inv);
    }
}

// ---------------------------------------------------------------------------
// Main: ratings[b,n] = P[b] . Qh[item[b,n]]; softmax over n.
// 4-lane groups: lane q4 loads uint4 #q4 and #(q4+4) of the 128B row.
// Per 32 samples: 4 idx LDG + 8 LDG.128 + 8 SHFL.
// ---------------------------------------------------------------------------
__global__ void __launch_bounds__(256) main_kernel(
        const int* __restrict__ iidx,
        float* __restrict__ out, int ns) {
    __shared__ __align__(16) uint4 Psh[8];
    __shared__ __align__(16) float rat[1024];
    __shared__ float red[8];
    int b = blockIdx.x;
    int t = threadIdx.x;
    if (t < 8) Psh[t] = ((const uint4*)(g_Ph + b * 64))[t];
    __syncthreads();

    int w = t >> 5, lane = t & 31, g8 = lane >> 2, q4 = lane & 3;
    uint4 prA = Psh[q4];                  // aspect-halves 8q4..8q4+7
    uint4 prB = Psh[q4 + 4];
    __half2 pa0 = *(__half2*)&prA.x, pa1 = *(__half2*)&prA.y;
    __half2 pa2 = *(__half2*)&prA.z, pa3 = *(__half2*)&prA.w;
    __half2 pb0 = *(__half2*)&prB.x, pb1 = *(__half2*)&prB.y;
    __half2 pb2 = *(__half2*)&prB.z, pb3 = *(__half2*)&prB.w;
    const int* idxrow = iidx + (size_t)b * ns;
    int nsp = (ns + 255) & ~255;          // padded bound (256 samples/iter)

    for (int s0 = w * 32; s0 < nsp; s0 += 256) {
        uint4 ra[4], rb[4];
        // -------- batched load phase: no consume until all issued --------
#pragma unroll
        for (int k = 0; k < 4; k++) {
            int s = s0 + k * 8 + g8;
            int item = (s < ns) ? idxrow[s] : 0;
            const uint4* row = (const uint4*)(g_Qh + (size_t)item * NA);
            ra[k] = row[q4];
            rb[k] = row[q4 + 4];
        }
        // -------- compute + reduce phase (all-fp16 dot) --------
#pragma unroll
        for (int k = 0; k < 4; k++) {
            __half2 acc = __hmul2(*(__half2*)&ra[k].x, pa0);
            acc = __hfma2(*(__half2*)&ra[k].y, pa1, acc);
            acc = __hfma2(*(__half2*)&ra[k].z, pa2, acc);
            acc = __hfma2(*(__half2*)&ra[k].w, pa3, acc);
            acc = __hfma2(*(__half2*)&rb[k].x, pb0, acc);
            acc = __hfma2(*(__half2*)&rb[k].y, pb1, acc);
            acc = __hfma2(*(__half2*)&rb[k].z, pb2, acc);
            acc = __hfma2(*(__half2*)&rb[k].w, pb3, acc);
            float2 f = __half22float2(acc);
            float r = f.x + f.y;
            r += __shfl_xor_sync(0xffffffffu, r, 1);
            r += __shfl_xor_sync(0xffffffffu, r, 2);
            int s = s0 + k * 8 + g8;
            if (s < ns && q4 == 0) rat[s] = r;
        }
    }
    __syncthreads();

    // block softmax over rat[0..ns)
    float m = -1e30f;
    for (int s = t; s < ns; s += 256) m = fmaxf(m, rat[s]);
#pragma unroll
    for (int o = 16; o; o >>= 1) m = fmaxf(m, __shfl_xor_sync(0xffffffffu, m, o));
    if (lane == 0) red[w] = m;
    __syncthreads();
    if (t == 0) {
        float v = red[0];
#pragma unroll
        for (int i = 1; i < 8; i++) v = fmaxf(v, red[i]);
        red[0] = v;
    }
    __syncthreads();
    m = red[0];
    __syncthreads();   // protect red[] before sum phase reuses it

    float sum = 0.f;
    for (int s = t; s < ns; s += 256) {
        float e = __expf(rat[s] - m);
        rat[s] = e;
        sum += e;
    }
#pragma unroll
    for (int o = 16; o; o >>= 1) sum += __shfl_xor_sync(0xffffffffu, sum, o);
    if (lane == 0) red[w] = sum;
    __syncthreads();
    if (t == 0) {
        float v = red[0];
#pragma unroll
        for (int i = 1; i < 8; i++) v += red[i];
        red[0] = v;
    }
    __syncthreads();
    float inv = __fdividef(1.f, red[0]);
    float* orow = out + (size_t)b * ns;
    for (int s = t; s < ns; s += 256) orow[s] = rat[s] * inv;
}

// ---------------------------------------------------------------------------
// Launch
// ---------------------------------------------------------------------------
extern "C" void kernel_launch(void* const* d_in, const int* in_sizes, int n_in,
                              void* d_out, int out_size) {
    const int*   uidx = (const int*)d_in[0];
    const int*   iidx = (const int*)d_in[1];
    const float* Uemb = (const float*)d_in[2];
    const float* Iemb = (const float*)d_in[3];
    const float* A    = (const float*)d_in[4];
    const float* Rel  = (const float*)d_in[5];
    const float* bias = (const float*)d_in[6];
    float* out = (float*)d_out;

    int bz    = in_sizes[0];
    int ns    = in_sizes[1] / bz;
    int nitem = in_sizes[3] / D;

    int QB = (nitem + 63) / 64;
    int PB = (bz + 7) / 8;

    prep_kernel<<<QB + PB, 256>>>(uidx, Uemb, Iemb, A, Rel, bias, bz, nitem, QB);
    main_kernel<<<bz, 256>>>(iidx, out, ns);
}

// round 10
// speedup vs baseline: 1.0050x; 1.0050x over previous
#include <cuda_runtime.h>
#include <cuda_fp16.h>

#define D  64
#define NA 64
#define MAX_ITEM 100000
#define MAX_BZ   1024

// Scratch tables (allocation-free: __device__ globals)
__device__ __align__(16) __half g_Ph[MAX_BZ * NA];             // 128 KB fp16 P
__device__ __align__(16) __half g_Qh[(size_t)MAX_ITEM * NA];   // 12.8 MB fp16 Qd+bias

// ---- packed f32x2 FMA (Blackwell): acc = a*b + acc, lanewise on 2 floats ----
__device__ __forceinline__ void ffma2(unsigned long long& acc,
                                      unsigned long long a,
                                      unsigned long long b) {
    asm("fma.rn.f32x2 %0, %1, %2, %0;" : "+l"(acc) : "l"(a), "l"(b));
}
union F2U { float2 f; unsigned long long u; };
union F4U { float4 f; struct { unsigned long long lo, hi; } u; };

// A row stride: 68 floats = 272 B. 16B-aligned rows (272%16==0) AND
// inter-lane bank stride 68%32==4 -> each 8-lane LDS.128 phase hits distinct
// bank quads: conflict-free at the 4-wavefront floor.
#define A_STRIDE 68

// ---------------------------------------------------------------------------
// Fused prep (identical to the passing R8 version): blocks [0, QB) -> fp16 Qd
// table (+bias folded); [QB,QB+PB) -> P. Lane owns aspects (l, l+32).
// ---------------------------------------------------------------------------
__global__ void __launch_bounds__(256) prep_kernel(
        const int* __restrict__ uidx,
        const float* __restrict__ Uemb,
        const float* __restrict__ Iemb,
        const float* __restrict__ A,
        const float* __restrict__ Rel,
        const float* __restrict__ bias,
        int bz, int nitem, int QB) {
    __shared__ __align__(16) float  A_s[64 * A_STRIDE];  // 17.4 KB row-major padded
    __shared__ __align__(16) float  sR[128];             // qd: RpA|RnA ; p: RuA
    __shared__ __align__(16) float4 Ism[8][128];         // 8 items x 64 f /warp

    int t = threadIdx.x;
    for (int idx = t; idx < 64 * 64; idx += 256)
        A_s[(idx >> 6) * A_STRIDE + (idx & 63)] = A[idx];  // coalesced fill
    __syncthreads();

    int w = t >> 5, lane = t & 31;
    bool isQ = blockIdx.x < QB;

    // ---- per-block relation projections (A from smem, Rel broadcast) ----
    if (isQ) {
        if (t < 128) {
            int rr = 1 + (t >> 6);       // 1 = Rip, 2 = Rin
            int a  = t & 63;
            const float* rv = Rel + rr * D;
            const float* ar = A_s + a * A_STRIDE;
            float s = 0.f;
#pragma unroll
            for (int d = 0; d < 64; d++) s += rv[d] * ar[d];
            sR[t] = s;                    // [0,64)=RpA, [64,128)=RnA
        }
    } else {
        if (t < 64) {
            const float* ar = A_s + t * A_STRIDE;
            float s = 0.f;
#pragma unroll
            for (int d = 0; d < 64; d++) s += Rel[d] * ar[d];
            sR[t] = s;                    // RuA
        }
    }
    __syncthreads();

    if (isQ) {
        // ======== Qd blocks: 8 warps x 8 items = 64 items/block ========
        float rp0 = sR[lane],      rp1 = sR[lane + 32];   // aspects l, l+32
        float rn0 = sR[64 + lane], rn1 = sR[96 + lane];
        int base8 = blockIdx.x * 64 + w * 8;              // 8 consecutive items
        if (base8 < nitem) {                              // nitem % 8 == 0
            // Item tile: straight linear copy, conflict-free, coalesced.
            const float4* g4 = (const float4*)(Iemb + (size_t)base8 * D);
#pragma unroll
            for (int u = 0; u < 4; u++) Ism[w][lane + 32 * u] = g4[lane + 32 * u];
            __syncwarp();

            unsigned long long acc[8][2];
#pragma unroll
            for (int j = 0; j < 8; j++) { acc[j][0] = 0ull; acc[j][1] = 0ull; }

            const float* Arow0 = A_s + lane * A_STRIDE;          // aspect l
            const float* Arow1 = A_s + (lane + 32) * A_STRIDE;   // aspect l+32
            const float4* irow = Ism[w];
#pragma unroll 4
            for (int dc = 0; dc < 16; dc++) {          // 4 d per iteration
                F4U a0; a0.f = *(const float4*)(Arow0 + 4 * dc);   // LDS.128 cf
                F4U a1; a1.f = *(const float4*)(Arow1 + 4 * dc);   // LDS.128 cf
#pragma unroll
                for (int j = 0; j < 8; j++) {
                    F4U iv; iv.f = irow[j * 16 + dc];              // LDS.128 bcast
                    ffma2(acc[j][0], iv.u.lo, a0.u.lo);
                    ffma2(acc[j][1], iv.u.lo, a1.u.lo);
                    ffma2(acc[j][0], iv.u.hi, a0.u.hi);
                    ffma2(acc[j][1], iv.u.hi, a1.u.hi);
                }
            }

#pragma unroll
            for (int j = 0; j < 8; j++) {
                F2U c0; c0.u = acc[j][0];
                F2U c1; c1.u = acc[j][1];
                float L0 = c0.f.x + c0.f.y;           // horizontal d-combine
                float L1 = c1.f.x + c1.f.y;
                // shift-free softmax: |logit| <~ 50 << 88 (fp32 exp overflow)
                float ep0 = __expf(L0 + rp0), ep1 = __expf(L1 + rp1);
                float en0 = __expf(L0 + rn0), en1 = __expf(L1 + rn1);
                float sp = ep0 + ep1, sn = en0 + en1;
#pragma unroll
                for (int o = 16; o; o >>= 1) {
                    sp += __shfl_xor_sync(0xffffffffu, sp, o);
                    sn += __shfl_xor_sync(0xffffffffu, sn, o);
                }
                float ipv = __fdividef(1.f, sp);
                float inv = __fdividef(1.f, sn);
                float bb  = bias[base8 + j];          // warp-uniform broadcast
                __half* orow = g_Qh + (size_t)(base8 + j) * NA;
                orow[lane]      = __float2half_rn(ep0 * ipv - en0 * inv + bb);
                orow[lane + 32] = __float2half_rn(ep1 * ipv - en1 * inv + bb);
            }
        }
    } else {
        // ================= P blocks: 8 users/block =================
        float ru0 = sR[lane], ru1 = sR[lane + 32];
        int row = (blockIdx.x - QB) * 8 + w;
        if (row >= bz) return;
        const float* U = Uemb + (size_t)uidx[row] * D;
        float* us = (float*)Ism[w];
        ((float2*)us)[lane] = ((const float2*)U)[lane];
        __syncwarp();

        const float* Arow0 = A_s + lane * A_STRIDE;
        const float* Arow1 = A_s + (lane + 32) * A_STRIDE;
        float acc0 = 0.f, acc1 = 0.f;
#pragma unroll
        for (int d = 0; d < 64; d++) {
            float u = us[d];
            acc0 += u * Arow0[d];
            acc1 += u * Arow1[d];
        }
        float l0 = acc0 + ru0, l1 = acc1 + ru1;
        float m = fmaxf(l0, l1);
#pragma unroll
        for (int o = 16; o; o >>= 1) m = fmaxf(m, __shfl_xor_sync(0xffffffffu, m, o));
        float e0 = __expf(l0 - m), e1 = __expf(l1 - m);
        float s = e0 + e1;
#pragma unroll
        for (int o = 16; o; o >>= 1) s += __shfl_xor_sync(0xffffffffu, s, o);
        float inv = __fdividef(1.f, s);
        __half* prow = g_Ph + row * NA;
        prow[lane]      = __float2half_rn(e0 * inv);
        prow[lane + 32] = __float2half_rn(e1 * inv);
    }
}

// ---------------------------------------------------------------------------
// Main: ratings[b,n] = P[b] . Qh[item[b,n]]; softmax over n.
// 4-lane groups: lane q4 loads uint4 #q4 and #(q4+4) of the 128B row.
// Software-pipelined indices: iteration j+1's idx loads issue while iteration
// j's row gathers are in flight -> one L2 round trip per iteration, not two.
// Row gathers via __ldcg (L2-resident table; skip L1 allocation).
// ---------------------------------------------------------------------------
__global__ void __launch_bounds__(256) main_kernel(
        const int* __restrict__ iidx,
        float* __restrict__ out, int ns) {
    __shared__ __align__(16) uint4 Psh[8];
    __shared__ __align__(16) float rat[1024];
    __shared__ float red[8];
    int b = blockIdx.x;
    int t = threadIdx.x;
    if (t < 8) Psh[t] = ((const uint4*)(g_Ph + b * 64))[t];
    __syncthreads();

    int w = t >> 5, lane = t & 31, g8 = lane >> 2, q4 = lane & 3;
    uint4 prA = Psh[q4];                  // aspect-halves 8q4..8q4+7
    uint4 prB = Psh[q4 + 4];
    __half2 pa0 = *(__half2*)&prA.x, pa1 = *(__half2*)&prA.y;
    __half2 pa2 = *(__half2*)&prA.z, pa3 = *(__half2*)&prA.w;
    __half2 pb0 = *(__half2*)&prB.x, pb1 = *(__half2*)&prB.y;
    __half2 pb2 = *(__half2*)&prB.z, pb3 = *(__half2*)&prB.w;
    const int* idxrow = iidx + (size_t)b * ns;
    int nsp = (ns + 255) & ~255;          // padded bound (256 samples/iter)

    // prologue: indices for first iteration
    int cidx[4];
    {
        int s0 = w * 32;
#pragma unroll
        for (int k = 0; k < 4; k++) {
            int s = s0 + k * 8 + g8;
            cidx[k] = (s < ns) ? idxrow[s] : 0;
        }
    }

    for (int s0 = w * 32; s0 < nsp; s0 += 256) {
        uint4 ra[4], rb[4];
        // -------- row gathers (indices already resident) --------
#pragma unroll
        for (int k = 0; k < 4; k++) {
            const uint4* row = (const uint4*)(g_Qh + (size_t)cidx[k] * NA);
            ra[k] = __ldcg(row + q4);
            rb[k] = __ldcg(row + q4 + 4);
        }
        // -------- prefetch next iteration's indices (overlaps row latency) ----
        int nidx[4] = {0, 0, 0, 0};
        int s1 = s0 + 256;
        if (s1 < nsp) {
#pragma unroll
            for (int k = 0; k < 4; k++) {
                int s = s1 + k * 8 + g8;
                nidx[k] = (s < ns) ? idxrow[s] : 0;
            }
        }
        // -------- compute + reduce (all-fp16 dot) --------
#pragma unroll
        for (int k = 0; k < 4; k++) {
            __half2 acc = __hmul2(*(__half2*)&ra[k].x, pa0);
            acc = __hfma2(*(__half2*)&ra[k].y, pa1, acc);
            acc = __hfma2(*(__half2*)&ra[k].z, pa2, acc);
            acc = __hfma2(*(__half2*)&ra[k].w, pa3, acc);
            acc = __hfma2(*(__half2*)&rb[k].x, pb0, acc);
            acc = __hfma2(*(__half2*)&rb[k].y, pb1, acc);
            acc = __hfma2(*(__half2*)&rb[k].z, pb2, acc);
            acc = __hfma2(*(__half2*)&rb[k].w, pb3, acc);
            float2 f = __half22float2(acc);
            float r = f.x + f.y;
            r += __shfl_xor_sync(0xffffffffu, r, 1);
            r += __shfl_xor_sync(0xffffffffu, r, 2);
            int s = s0 + k * 8 + g8;
            if (s < ns && q4 == 0) rat[s] = r;
        }
#pragma unroll
        for (int k = 0; k < 4; k++) cidx[k] = nidx[k];
    }
    __syncthreads();

    // block softmax over rat[0..ns)
    float m = -1e30f;
    for (int s = t; s < ns; s += 256) m = fmaxf(m, rat[s]);
#pragma unroll
    for (int o = 16; o; o >>= 1) m = fmaxf(m, __shfl_xor_sync(0xffffffffu, m, o));
    if (lane == 0) red[w] = m;
    __syncthreads();
    if (t == 0) {
        float v = red[0];
#pragma unroll
        for (int i = 1; i < 8; i++) v = fmaxf(v, red[i]);
        red[0] = v;
    }
    __syncthreads();
    m = red[0];
    __syncthreads();   // protect red[] before sum phase reuses it

    float sum = 0.f;
    for (int s = t; s < ns; s += 256) {
        float e = __expf(rat[s] - m);
        rat[s] = e;
        sum += e;
    }
#pragma unroll
    for (int o = 16; o; o >>= 1) sum += __shfl_xor_sync(0xffffffffu, sum, o);
    if (lane == 0) red[w] = sum;
    __syncthreads();
    if (t == 0) {
        float v = red[0];
#pragma unroll
        for (int i = 1; i < 8; i++) v += red[i];
        red[0] = v;
    }
    __syncthreads();
    float inv = __fdividef(1.f, red[0]);
    float* orow = out + (size_t)b * ns;
    for (int s = t; s < ns; s += 256) orow[s] = rat[s] * inv;
}

// ---------------------------------------------------------------------------
// Launch
// ---------------------------------------------------------------------------
extern "C" void kernel_launch(void* const* d_in, const int* in_sizes, int n_in,
                              void* d_out, int out_size) {
    const int*   uidx = (const int*)d_in[0];
    const int*   iidx = (const int*)d_in[1];
    const float* Uemb = (const float*)d_in[2];
    const float* Iemb = (const float*)d_in[3];
    const float* A    = (const float*)d_in[4];
    const float* Rel  = (const float*)d_in[5];
    const float* bias = (const float*)d_in[6];
    float* out = (float*)d_out;

    int bz    = in_sizes[0];
    int ns    = in_sizes[1] / bz;
    int nitem = in_sizes[3] / D;

    int QB = (nitem + 63) / 64;
    int PB = (bz + 7) / 8;

    prep_kernel<<<QB + PB, 256>>>(uidx, Uemb, Iemb, A, Rel, bias, bz, nitem, QB);
    main_kernel<<<bz, 256>>>(iidx, out, ns);
}